// round 17
// baseline (speedup 1.0000x reference)
#include <cuda_runtime.h>
#include <cuda_fp16.h>

#define BB 8
#define HH 512
#define WW 512
#define HW (HH * WW)

#define TX 32
#define TYW 8                  // 256 threads
#define PY 8
#define TILE_H (TYW * PY)      // 64
#define SW 38                  // logical halo cols
#define SH (TILE_H + 6)        // 70
#define ROWP 20                // uint2 slots per row (40 halves)
#define BOFF 1416              // copyB uint2 offset: 1416*8=11328 B == 64 mod 128 -> bank-disjoint
#define NSLOT 2816             // total uint2 (A:1400 used, B @1416 +1400)
#define NBLOCKS ((WW / TX) * (HH / TILE_H) * BB)   // 1024
#define NQUAD (SH * 10)        // 700 quads (fast path)

__device__ unsigned long long g_pack = 0ULL;

__device__ __forceinline__ unsigned gt2(unsigned a, unsigned b) {
    return __hgt2_mask(*(const __half2*)&a, *(const __half2*)&b);
}

__global__ __launch_bounds__(TX * TYW, 5)
void census_fused(const float* __restrict__ pred, const float* __restrict__ tgt,
                  float* __restrict__ out) {
    // slot u = {pred_u32 (2 halves), tgt_u32 (2 halves)}; copyB[i] = elem i+1
    __shared__ __align__(16) uint2 sm[NSLOT];
    __shared__ int wsum[TYW];
    unsigned short* smh = (unsigned short*)sm;   // slot u -> halves 4u..4u+3 [pLo,pHi,tLo,tHi]

    const int b  = blockIdx.z;
    const int x0 = blockIdx.x * TX;
    const int y0 = blockIdx.y * TILE_H;
    const int tid = threadIdx.y * TX + threadIdx.x;

    const float* __restrict__ pb = pred + (size_t)b * 3 * HW;
    const float* __restrict__ tb = tgt  + (size_t)b * 3 * HW;

    const bool interiorBlk = (blockIdx.x > 0 && blockIdx.x + 1 < gridDim.x &&
                              blockIdx.y > 0 && blockIdx.y + 1 < gridDim.y);

    if (interiorBlk) {
        // -------- fast halo: float4 quad loads, no reflect --------
        const int ax0 = x0 - 4;             // 16B-aligned quad start
#pragma unroll
        for (int it = 0; it < 3; it++) {
            int q = tid + it * (TX * TYW);
            if (q < NQUAD) {
                int ly = q / 10;
                int p  = q - ly * 10;       // quad 0..9, covers si 4p..4p+3
                int off = (y0 + ly - 3) * WW + ax0 + 4 * p;
                float4 pr = *(const float4*)(pb + off);
                float4 pg = *(const float4*)(pb + HW + off);
                float4 pc = *(const float4*)(pb + 2 * HW + off);
                float4 tr = *(const float4*)(tb + off);
                float4 tg = *(const float4*)(tb + HW + off);
                float4 tc = *(const float4*)(tb + 2 * HW + off);
                __half2 hp01 = __floats2half2_rn(
                    fmaf(0.299f, pr.x, fmaf(0.587f, pg.x, 0.114f * pc.x)),
                    fmaf(0.299f, pr.y, fmaf(0.587f, pg.y, 0.114f * pc.y)));
                __half2 hp23 = __floats2half2_rn(
                    fmaf(0.299f, pr.z, fmaf(0.587f, pg.z, 0.114f * pc.z)),
                    fmaf(0.299f, pr.w, fmaf(0.587f, pg.w, 0.114f * pc.w)));
                __half2 ht01 = __floats2half2_rn(
                    fmaf(0.299f, tr.x, fmaf(0.587f, tg.x, 0.114f * tc.x)),
                    fmaf(0.299f, tr.y, fmaf(0.587f, tg.y, 0.114f * tc.y)));
                __half2 ht23 = __floats2half2_rn(
                    fmaf(0.299f, tr.z, fmaf(0.587f, tg.z, 0.114f * tc.z)),
                    fmaf(0.299f, tr.w, fmaf(0.587f, tg.w, 0.114f * tc.w)));
                unsigned p01 = *(unsigned*)&hp01, p23 = *(unsigned*)&hp23;
                unsigned t01 = *(unsigned*)&ht01, t23 = *(unsigned*)&ht23;
                int ua = ly * ROWP + 2 * p;           // even -> 16B aligned
                *(uint4*)&sm[ua] = make_uint4(p01, t01, p23, t23);   // copyA
                // copyB: halves h hold elem h+1
                int ub = BOFF + ly * ROWP + 2 * p;    // v = 2p: elems (4p+1, 4p+2)
                sm[ub] = make_uint2(__funnelshift_r(p01, p23, 16),
                                    __funnelshift_r(t01, t23, 16));
                if (p > 0) {                          // elem 4p -> slot v=2p-1 hi halves
                    smh[4 * (ub - 1) + 1] = (unsigned short)(p01 & 0xFFFFu);
                    smh[4 * (ub - 1) + 3] = (unsigned short)(t01 & 0xFFFFu);
                }
                smh[4 * (ub + 1) + 0] = (unsigned short)(p23 >> 16);  // elem 4p+3
                smh[4 * (ub + 1) + 2] = (unsigned short)(t23 >> 16);
            }
        }
    } else {
        // -------- border halo: scalar loads with reflect padding --------
        for (int idx = tid; idx < SH * SW; idx += TX * TYW) {
            int ly = idx / SW;
            int lx = idx - ly * SW;
            int gy = y0 + ly - 3;
            gy = (gy < 0) ? -gy : ((gy >= HH) ? 2 * HH - 2 - gy : gy);
            int gx = x0 + lx - 3;
            gx = (gx < 0) ? -gx : ((gx >= WW) ? 2 * WW - 2 - gx : gx);
            int off = gy * WW + gx;
            float gp = fmaf(0.299f, pb[off], fmaf(0.587f, pb[HW + off], 0.114f * pb[2 * HW + off]));
            float gt = fmaf(0.299f, tb[off], fmaf(0.587f, tb[HW + off], 0.114f * tb[2 * HW + off]));
            unsigned short hp = __half_as_ushort(__float2half_rn(gp));
            unsigned short ht = __half_as_ushort(__float2half_rn(gt));
            int si = lx + 1;                          // storage index 1..38
            int sa = ly * ROWP + (si >> 1);
            smh[4 * sa + (si & 1)]     = hp;          // copyA
            smh[4 * sa + 2 + (si & 1)] = ht;
            int h = si - 1;                           // copyB half index
            int sb = BOFF + ly * ROWP + (h >> 1);
            smh[4 * sb + (h & 1)]     = hp;
            smh[4 * sb + 2 + (h & 1)] = ht;
        }
    }
    __syncthreads();

    // -------- census core: one LDS.64 yields (pred,tgt) u32 pair --------
    const int tx   = threadIdx.x;
    const int base = threadIdx.y * PY;
    const int hx2  = (tx + (tx & 1)) >> 1;            // window slot base
    const int cb2  = (tx & 1) ? 0 : BOFF;             // tx odd -> copyA, even -> copyB
    const unsigned csel = (tx & 1) ? 0x3232u : 0x1010u;  // center half broadcast

    unsigned cp2[PY], ct2[PY];
#pragma unroll
    for (int k = 0; k < PY; k++) {
        uint2 cw = sm[(base + k + 3) * ROWP + ((tx + 4) >> 1)];
        cp2[k] = __byte_perm(cw.x, 0, csel);
        ct2[k] = __byte_perm(cw.y, 0, csel);
    }

    unsigned accM = 0, accA = 0;    // SIMD 16-bit field accumulators
#pragma unroll
    for (int r = 0; r < PY + 6; r++) {
        const int rb = cb2 + (base + r) * ROWP + hx2;
        uint2 w0 = sm[rb], w1 = sm[rb + 1], w2 = sm[rb + 2], w3 = sm[rb + 3];
#pragma unroll
        for (int k = 0; k < PY; k++) {
            const int dy = r - 3 - k;
            if (dy < -3 || dy > 3) continue;          // compile-time pruned
            unsigned x0m = gt2(cp2[k], w0.x) ^ gt2(ct2[k], w0.y);
            unsigned x1m = gt2(cp2[k], w1.x) ^ gt2(ct2[k], w1.y);
            unsigned x2m = gt2(cp2[k], w2.x) ^ gt2(ct2[k], w2.y);
            unsigned x3m = gt2(cp2[k], w3.x) ^ gt2(ct2[k], w3.y);
            accM = __vsub2(accM, x0m);   // 0xFFFF field == -1 -> +1 per mismatch
            accM = __vsub2(accM, x1m);
            accM = __vsub2(accM, x2m);
            accA = __vsub2(accA, x3m);   // hi lane (dx=+4) invalid -> discarded
            // center self-compare (dy==0, dx==0 lane) is 0 automatically
        }
    }
    int cnt = (int)(accM & 0xFFFFu) + (int)(accM >> 16) + (int)(accA & 0xFFFFu);

    // Warp + block reduction
    cnt = __reduce_add_sync(0xffffffffu, cnt);
    if (tx == 0) wsum[threadIdx.y] = cnt;
    __syncthreads();

    if (tid == 0) {
        int v = 0;
#pragma unroll
        for (int w = 0; w < TYW; w++) v += wsum[w];
        unsigned long long old =
            atomicAdd(&g_pack, (unsigned long long)v + (1ULL << 40));
        if ((old >> 40) == NBLOCKS - 1) {
            unsigned long long tot = (old & ((1ULL << 40) - 1)) + (unsigned long long)v;
            const double denom = 48.0 * (double)BB * (double)HW;  // 100663296
            out[0] = (float)((double)tot / denom);
            g_pack = 0ULL;    // reset for next graph replay
        }
    }
}

extern "C" void kernel_launch(void* const* d_in, const int* in_sizes, int n_in,
                              void* d_out, int out_size) {
    const float* pred = (const float*)d_in[0];
    const float* tgt  = (const float*)d_in[1];
    float* out = (float*)d_out;
    (void)in_sizes; (void)n_in; (void)out_size;

    dim3 bdim(TX, TYW);
    dim3 gdim(WW / TX, HH / TILE_H, BB);
    census_fused<<<gdim, bdim>>>(pred, tgt, out);
}